// round 16
// baseline (speedup 1.0000x reference)
#include <cuda_runtime.h>
#include <cuda_fp16.h>
#include <cstdint>

#define NN   50000
#define NE   800000
#define NB   ((NN + 255) / 256)

// ---------------- scratch (device globals; no dynamic allocation) ----------
__device__ int     g_deg[NN];
__device__ int     g_cur[NN];
__device__ float   g_dinv[NN];
__device__ __half  g_dinvh[NN];
__device__ int     g_off[NN + 1];
__device__ int     g_csr[NE];
__device__ __half  g_wedge[NE];     // per-edge weight dinvh[src], csr-order
__device__ int     g_bsum[NB];
__device__ int     g_boff[NB];
__device__ __half2 g_T[(size_t)NN * 128];
__device__ __half2 g_H[(size_t)NN * 128];
__device__ __half2 g_G[(size_t)NN * 128];
__device__ float   g_Wcat[256 * 256];
__device__ float   g_bcat[256];

__device__ __forceinline__ uint32_t h2u(__half2 h) {
    return *reinterpret_cast<uint32_t*>(&h);
}
__device__ __forceinline__ void ldsm_x4(uint32_t* r, uint32_t saddr) {
    asm volatile("ldmatrix.sync.aligned.m8n8.x4.shared.b16 {%0,%1,%2,%3}, [%4];"
                 : "=r"(r[0]), "=r"(r[1]), "=r"(r[2]), "=r"(r[3]) : "r"(saddr));
}

// ---------------- graph prep (6 launches) -----------------------------------
__global__ void initwcat_kernel(const float* __restrict__ Wmu, const float* __restrict__ Wls,
                                const float* __restrict__ bmu, const float* __restrict__ bls) {
    int i = blockIdx.x * 256 + threadIdx.x;   // grid covers 65536
    if (i < NN) { g_deg[i] = 1; g_cur[i] = 0; }
    if (i < 256) g_bcat[i] = (i < 128) ? bmu[i] : bls[i - 128];
    int k = i >> 8, c = i & 255;
    g_Wcat[i] = (c < 128) ? Wmu[k * 128 + c] : Wls[k * 128 + (c - 128)];
}
__global__ void count_kernel(const int* __restrict__ dst) {
    int e = blockIdx.x * blockDim.x + threadIdx.x;
    if (e < NE) atomicAdd(&g_deg[dst[e]], 1);
}
__global__ void blocksum_kernel() {
    int i = blockIdx.x * 256 + threadIdx.x;
    int d = (i < NN) ? g_deg[i] : 1;
    if (i < NN) {
        float r = rsqrtf((float)d);
        g_dinv[i]  = r;
        g_dinvh[i] = __float2half_rn(r);
    }
    int v = (i < NN) ? d - 1 : 0;
#pragma unroll
    for (int o = 16; o; o >>= 1) v += __shfl_down_sync(0xffffffffu, v, o);
    __shared__ int ws[8];
    if ((threadIdx.x & 31) == 0) ws[threadIdx.x >> 5] = v;
    __syncthreads();
    if (threadIdx.x < 8) {
        int s = ws[threadIdx.x];
#pragma unroll
        for (int o = 4; o; o >>= 1) s += __shfl_down_sync(0xffu, s, o);
        if (threadIdx.x == 0) g_bsum[blockIdx.x] = s;
    }
}
__global__ void bscan_kernel() {
    __shared__ int sh[256];
    int t = threadIdx.x;
    int v = (t < NB) ? g_bsum[t] : 0;
    sh[t] = v; __syncthreads();
    for (int o = 1; o < 256; o <<= 1) {
        int u = (t >= o) ? sh[t - o] : 0;
        __syncthreads(); sh[t] += u; __syncthreads();
    }
    if (t < NB) g_boff[t] = sh[t] - v;
}
__global__ void offsets_kernel() {
    __shared__ int sh[256];
    int b = blockIdx.x, t = threadIdx.x;
    int i = b * 256 + t;
    int v = (i < NN) ? g_deg[i] - 1 : 0;
    sh[t] = v; __syncthreads();
    for (int o = 1; o < 256; o <<= 1) {
        int u = (t >= o) ? sh[t - o] : 0;
        __syncthreads(); sh[t] += u; __syncthreads();
    }
    int excl = sh[t] - v + g_boff[b];
    if (i < NN)      g_off[i]  = excl;
    if (i == NN - 1) g_off[NN] = excl + v;
}
// fill: CSR indices + per-edge weight (dinvh ready: blocksum ran earlier)
__global__ void fill_kernel(const int* __restrict__ src, const int* __restrict__ dst) {
    int e = blockIdx.x * blockDim.x + threadIdx.x;
    if (e < NE) {
        int s = src[e];
        int d = dst[e];
        int pos = g_off[d] + atomicAdd(&g_cur[d], 1);
        g_csr[pos]   = s;
        g_wedge[pos] = g_dinvh[s];
    }
}

// ---------------- aggregation: warp/node, 8-edge MLP batches ---------------
// weight loads stream from g_wedge (independent of the csr->row chain)
__global__ void agg_h(const __half2* __restrict__ F, __half2* __restrict__ O,
                      const float* __restrict__ bias) {
    int gw = (blockIdx.x * blockDim.x + threadIdx.x) >> 5;
    if (gw >= NN) return;
    int lane = threadIdx.x & 31;

    float di = g_dinv[gw];
    float a[8];
    {
        uint4 v = *((const uint4*)(F + (size_t)gw * 128) + lane);
        const __half2* h = (const __half2*)&v;
#pragma unroll
        for (int j = 0; j < 4; j++) {
            float2 f = __half22float2(h[j]);
            a[2 * j]     = di * f.x;
            a[2 * j + 1] = di * f.y;
        }
    }

    int e = g_off[gw];
    const int eend = g_off[gw + 1];
    const __half2 hz = __floats2half2_rn(0.f, 0.f);

    while (e + 8 <= eend) {
        int s[8]; __half wv[8];
#pragma unroll
        for (int i = 0; i < 8; i++) s[i]  = g_csr[e + i];
#pragma unroll
        for (int i = 0; i < 8; i++) wv[i] = g_wedge[e + i];
        uint4 v[8];
#pragma unroll
        for (int i = 0; i < 8; i++)
            v[i] = *((const uint4*)(F + (size_t)s[i] * 128) + lane);
        __half2 pa0 = hz, pa1 = hz, pa2 = hz, pa3 = hz;
        __half2 pb0 = hz, pb1 = hz, pb2 = hz, pb3 = hz;
#pragma unroll
        for (int i = 0; i < 4; i++) {
            __half2 w2 = __half2half2(wv[i]);
            const __half2* h = (const __half2*)&v[i];
            pa0 = __hfma2(h[0], w2, pa0);
            pa1 = __hfma2(h[1], w2, pa1);
            pa2 = __hfma2(h[2], w2, pa2);
            pa3 = __hfma2(h[3], w2, pa3);
        }
#pragma unroll
        for (int i = 4; i < 8; i++) {
            __half2 w2 = __half2half2(wv[i]);
            const __half2* h = (const __half2*)&v[i];
            pb0 = __hfma2(h[0], w2, pb0);
            pb1 = __hfma2(h[1], w2, pb1);
            pb2 = __hfma2(h[2], w2, pb2);
            pb3 = __hfma2(h[3], w2, pb3);
        }
        float2 fa0 = __half22float2(pa0), fa1 = __half22float2(pa1);
        float2 fa2 = __half22float2(pa2), fa3 = __half22float2(pa3);
        float2 fb0 = __half22float2(pb0), fb1 = __half22float2(pb1);
        float2 fb2 = __half22float2(pb2), fb3 = __half22float2(pb3);
        a[0] += fa0.x + fb0.x; a[1] += fa0.y + fb0.y;
        a[2] += fa1.x + fb1.x; a[3] += fa1.y + fb1.y;
        a[4] += fa2.x + fb2.x; a[5] += fa2.y + fb2.y;
        a[6] += fa3.x + fb3.x; a[7] += fa3.y + fb3.y;
        e += 8;
    }
    if (e + 4 <= eend) {
        __half2 p0 = hz, p1 = hz, p2 = hz, p3 = hz;
#pragma unroll
        for (int i = 0; i < 4; i++) {
            int s = g_csr[e + i];
            __half2 w2 = __half2half2(g_wedge[e + i]);
            uint4 v = *((const uint4*)(F + (size_t)s * 128) + lane);
            const __half2* h = (const __half2*)&v;
            p0 = __hfma2(h[0], w2, p0);
            p1 = __hfma2(h[1], w2, p1);
            p2 = __hfma2(h[2], w2, p2);
            p3 = __hfma2(h[3], w2, p3);
        }
        float2 f0 = __half22float2(p0), f1 = __half22float2(p1);
        float2 f2 = __half22float2(p2), f3 = __half22float2(p3);
        a[0] += f0.x; a[1] += f0.y; a[2] += f1.x; a[3] += f1.y;
        a[4] += f2.x; a[5] += f2.y; a[6] += f3.x; a[7] += f3.y;
        e += 4;
    }
    for (; e < eend; e++) {
        int s = g_csr[e];
        float w = __half2float(g_wedge[e]);
        uint4 v = *((const uint4*)(F + (size_t)s * 128) + lane);
        const __half2* h = (const __half2*)&v;
#pragma unroll
        for (int j = 0; j < 4; j++) {
            float2 f = __half22float2(h[j]);
            a[2 * j]     += w * f.x;
            a[2 * j + 1] += w * f.y;
        }
    }
#pragma unroll
    for (int j = 0; j < 8; j++) a[j] *= di;

    uint4 o;
    __half2* oh = (__half2*)&o;
    if (bias) {
        const float4* bp = (const float4*)bias + lane * 2;
        float4 b0 = bp[0], b1 = bp[1];
        float bb[8] = {b0.x, b0.y, b0.z, b0.w, b1.x, b1.y, b1.z, b1.w};
#pragma unroll
        for (int j = 0; j < 4; j++) {
            float x0 = fmaxf(a[2 * j]     + bb[2 * j],     0.f);
            float x1 = fmaxf(a[2 * j + 1] + bb[2 * j + 1], 0.f);
            oh[j] = __floats2half2_rn(x0, x1);
        }
    } else {
#pragma unroll
        for (int j = 0; j < 4; j++)
            oh[j] = __floats2half2_rn(a[2 * j], a[2 * j + 1]);
    }
    *((uint4*)O + (size_t)gw * 32 + lane) = o;
}

// ---------------- FP16 tensor-core GEMM (m16n8k16, fp32 accum) -------------
__device__ __forceinline__ void mma_f16(float* d, const uint32_t* a, const uint32_t* b) {
    asm volatile(
        "mma.sync.aligned.m16n8k16.row.col.f32.f16.f16.f32 "
        "{%0,%1,%2,%3}, {%4,%5,%6,%7}, {%8,%9}, {%0,%1,%2,%3};"
        : "+f"(d[0]), "+f"(d[1]), "+f"(d[2]), "+f"(d[3])
        : "r"(a[0]), "r"(a[1]), "r"(a[2]), "r"(a[3]), "r"(b[0]), "r"(b[1]));
}

#define GBM 128
#define ASTRIDE 20
#define BSTRIDE 136

template <int MODE>
__global__ __launch_bounds__(256) void h16gemm_kernel(
    const void* __restrict__ Ain, const float* __restrict__ B,
    const float* __restrict__ bias, void* __restrict__ Cout, int M) {
    __shared__ uint32_t As[GBM * ASTRIDE];
    __shared__ uint32_t Bs[16 * BSTRIDE];

    const int t = threadIdx.x;
    const int lane = t & 31;
    const int warp = t >> 5;
    const int warpM = warp >> 2;
    const int warpN = warp & 3;
    const int l4 = lane >> 2, k4 = lane & 3;
    const int rowBase = blockIdx.x * GBM;
    const int colBase = blockIdx.y * 128;
    const int mBase = warpM * 64;
    const int nBase = warpN * 32;

    const int aRow  = (MODE == 0) ? (t >> 3) : (t >> 2);
    const int aK2   = (MODE == 0) ? ((t & 7) << 1) : ((t & 3) << 2);
    const int bK2 = t >> 5;
    const int bNc = (t & 31) << 2;

    const uint32_t asBase = (uint32_t)__cvta_generic_to_shared(As);
    const int lmRow = lane & 15;
    const int lmK   = (lane >> 4) << 2;

    float4 raf[4]; uint4 rah[2]; float4 rb0[2], rb1[2];
#pragma unroll
    for (int l = 0; l < 2; l++) {
        int k2 = bK2 + l * 8;
        rb0[l] = *(const float4*)(B + (size_t)(2 * k2)     * 256 + colBase + bNc);
        rb1[l] = *(const float4*)(B + (size_t)(2 * k2 + 1) * 256 + colBase + bNc);
    }
    if (MODE == 0) {
        const float* A = (const float*)Ain;
#pragma unroll
        for (int l = 0; l < 4; l++) {
            int gr = rowBase + aRow + l * 32;
            raf[l] = (gr < M) ? *(const float4*)(A + (size_t)gr * 256 + aK2 * 2)
                              : make_float4(0.f, 0.f, 0.f, 0.f);
        }
    } else {
        const __half2* A = (const __half2*)Ain;
#pragma unroll
        for (int l = 0; l < 2; l++) {
            int gr = rowBase + aRow + l * 64;
            rah[l] = (gr < M) ? *((const uint4*)(A + (size_t)gr * 128) + (aK2 >> 2))
                              : make_uint4(0u, 0u, 0u, 0u);
        }
    }

    float acc[4][4][4];
#pragma unroll
    for (int i = 0; i < 4; i++)
#pragma unroll
        for (int j = 0; j < 4; j++)
#pragma unroll
            for (int r = 0; r < 4; r++) acc[i][j][r] = 0.f;

    for (int it = 0; it < 8; it++) {
        if (MODE == 0) {
#pragma unroll
            for (int l = 0; l < 4; l++) {
                uint32_t* p = &As[(aRow + l * 32) * ASTRIDE + aK2];
                p[0] = h2u(__floats2half2_rn(raf[l].x, raf[l].y));
                p[1] = h2u(__floats2half2_rn(raf[l].z, raf[l].w));
            }
        } else {
#pragma unroll
            for (int l = 0; l < 2; l++)
                *(uint4*)&As[(aRow + l * 64) * ASTRIDE + aK2] = rah[l];
        }
#pragma unroll
        for (int l = 0; l < 2; l++) {
            uint4 u;
            u.x = h2u(__floats2half2_rn(rb0[l].x, rb1[l].x));
            u.y = h2u(__floats2half2_rn(rb0[l].y, rb1[l].y));
            u.z = h2u(__floats2half2_rn(rb0[l].z, rb1[l].z));
            u.w = h2u(__floats2half2_rn(rb0[l].w, rb1[l].w));
            *(uint4*)&Bs[(bK2 + l * 8) * BSTRIDE + bNc] = u;
        }
        __syncthreads();

        if (it < 7) {
            int k0 = (it + 1) * 32;
#pragma unroll
            for (int l = 0; l < 2; l++) {
                int k2 = (k0 >> 1) + bK2 + l * 8;
                rb0[l] = *(const float4*)(B + (size_t)(2 * k2)     * 256 + colBase + bNc);
                rb1[l] = *(const float4*)(B + (size_t)(2 * k2 + 1) * 256 + colBase + bNc);
            }
            if (MODE == 0) {
                const float* A = (const float*)Ain;
#pragma unroll
                for (int l = 0; l < 4; l++) {
                    int gr = rowBase + aRow + l * 32;
                    raf[l] = (gr < M) ? *(const float4*)(A + (size_t)gr * 256 + k0 + aK2 * 2)
                                      : make_float4(0.f, 0.f, 0.f, 0.f);
                }
            } else {
                const __half2* A = (const __half2*)Ain;
#pragma unroll
                for (int l = 0; l < 2; l++) {
                    int gr = rowBase + aRow + l * 64;
                    rah[l] = (gr < M) ? *((const uint4*)(A + (size_t)gr * 128) + ((k0 >> 1) + aK2) / 4)
                                      : make_uint4(0u, 0u, 0u, 0u);
                }
            }
        }

#pragma unroll
        for (int ks = 0; ks < 16; ks += 8) {
            uint32_t af[4][4], bf[4][2];
#pragma unroll
            for (int mi = 0; mi < 4; mi++) {
                uint32_t sa = asBase +
                    4u * ((uint32_t)(mBase + mi * 16 + lmRow) * ASTRIDE + ks + lmK);
                ldsm_x4(af[mi], sa);
            }
#pragma unroll
            for (int ni = 0; ni < 4; ni++) {
                int n = nBase + ni * 8 + l4;
                bf[ni][0] = Bs[(ks + k4) * BSTRIDE + n];
                bf[ni][1] = Bs[(ks + k4 + 4) * BSTRIDE + n];
            }
#pragma unroll
            for (int mi = 0; mi < 4; mi++)
#pragma unroll
                for (int ni = 0; ni < 4; ni++)
                    mma_f16(acc[mi][ni], af[mi], bf[ni]);
        }
        __syncthreads();
    }

#pragma unroll
    for (int mi = 0; mi < 4; mi++) {
        int r0 = rowBase + mBase + mi * 16 + l4;
        int r1 = r0 + 8;
#pragma unroll
        for (int ni = 0; ni < 4; ni++) {
            int cl = nBase + ni * 8 + k4 * 2;
            if (MODE == 0) {
                __half2* T = (__half2*)Cout;
                int c = colBase + cl;
                if (r0 < M) T[(size_t)r0 * 128 + (c >> 1)] =
                    __floats2half2_rn(acc[mi][ni][0], acc[mi][ni][1]);
                if (r1 < M) T[(size_t)r1 * 128 + (c >> 1)] =
                    __floats2half2_rn(acc[mi][ni][2], acc[mi][ni][3]);
            } else {
                float* Co = (float*)Cout + (blockIdx.y ? (size_t)NN * 128 : 0);
                float bv0 = bias[colBase + cl];
                float bv1 = bias[colBase + cl + 1];
                if (r0 < M) {
                    float2 o; o.x = acc[mi][ni][0] + bv0; o.y = acc[mi][ni][1] + bv1;
                    *(float2*)(Co + (size_t)r0 * 128 + cl) = o;
                }
                if (r1 < M) {
                    float2 o; o.x = acc[mi][ni][2] + bv0; o.y = acc[mi][ni][3] + bv1;
                    *(float2*)(Co + (size_t)r1 * 128 + cl) = o;
                }
            }
        }
    }
}

// ---------------- launch: fork prep || GEMM1, join before agg ---------------
extern "C" void kernel_launch(void* const* d_in, const int* in_sizes, int n_in,
                              void* d_out, int out_size) {
    const float* x    = (const float*)d_in[0];
    const int*   ei   = (const int*)d_in[1];
    const float* W1   = (const float*)d_in[2];
    const float* b1   = (const float*)d_in[3];
    const float* Wmu  = (const float*)d_in[4];
    const float* bmu  = (const float*)d_in[5];
    const float* Wls  = (const float*)d_in[6];
    const float* bls  = (const float*)d_in[7];
    float* out = (float*)d_out;

    const int* src = ei;
    const int* dst = ei + NE;

    __half2 *pT, *pH, *pG; float *pWcat, *pbcat;
    cudaGetSymbolAddress((void**)&pT, g_T);
    cudaGetSymbolAddress((void**)&pH, g_H);
    cudaGetSymbolAddress((void**)&pG, g_G);
    cudaGetSymbolAddress((void**)&pWcat, g_Wcat);
    cudaGetSymbolAddress((void**)&pbcat, g_bcat);

    cudaStream_t s1;
    cudaEvent_t evFork, evJoin;
    cudaStreamCreateWithFlags(&s1, cudaStreamNonBlocking);
    cudaEventCreateWithFlags(&evFork, cudaEventDisableTiming);
    cudaEventCreateWithFlags(&evJoin, cudaEventDisableTiming);

    cudaEventRecord(evFork, 0);
    cudaStreamWaitEvent(s1, evFork, 0);

    // side stream: graph prep (6 launches)
    initwcat_kernel<<<256, 256, 0, s1>>>(Wmu, Wls, bmu, bls);
    count_kernel<<<(NE + 255) / 256, 256, 0, s1>>>(dst);
    blocksum_kernel<<<NB, 256, 0, s1>>>();
    bscan_kernel<<<1, 256, 0, s1>>>();
    offsets_kernel<<<NB, 256, 0, s1>>>();
    fill_kernel<<<(NE + 255) / 256, 256, 0, s1>>>(src, dst);
    cudaEventRecord(evJoin, s1);

    // main stream: T = x @ W1
    dim3 ggrid((NN + GBM - 1) / GBM, 2);
    h16gemm_kernel<0><<<ggrid, 256>>>(x, W1, nullptr, pT, NN);

    cudaStreamWaitEvent(0, evJoin, 0);
    agg_h<<<(NN * 32 + 255) / 256, 256>>>(pT, pH, b1);
    agg_h<<<(NN * 32 + 255) / 256, 256>>>(pH, pG, nullptr);
    h16gemm_kernel<1><<<ggrid, 256>>>(pG, pWcat, pbcat, out, NN);
}

// round 17
// speedup vs baseline: 1.5300x; 1.5300x over previous
#include <cuda_runtime.h>
#include <cuda_fp16.h>
#include <cstdint>

#define NN   50000
#define NE   800000
#define NB   ((NN + 255) / 256)

// ---------------- scratch (device globals; no dynamic allocation) ----------
__device__ int     g_deg[NN];
__device__ int     g_cur[NN];
__device__ float   g_dinv[NN];
__device__ __half  g_dinvh[NN];
__device__ int     g_off[NN + 1];
__device__ int     g_csr[NE];
__device__ int     g_bsum[NB];
__device__ int     g_boff[NB];
__device__ __half2 g_T[(size_t)NN * 128];
__device__ __half2 g_H[(size_t)NN * 128];   // pre-scaled: dinv_i * relu(...)
__device__ __half2 g_G[(size_t)NN * 128];
__device__ float   g_Wcat[256 * 256];
__device__ float   g_bcat[256];

__device__ __forceinline__ uint32_t h2u(__half2 h) {
    return *reinterpret_cast<uint32_t*>(&h);
}
__device__ __forceinline__ void ldsm_x4(uint32_t* r, uint32_t saddr) {
    asm volatile("ldmatrix.sync.aligned.m8n8.x4.shared.b16 {%0,%1,%2,%3}, [%4];"
                 : "=r"(r[0]), "=r"(r[1]), "=r"(r[2]), "=r"(r[3]) : "r"(saddr));
}

// ---------------- graph prep (6 launches) -----------------------------------
__global__ void initwcat_kernel(const float* __restrict__ Wmu, const float* __restrict__ Wls,
                                const float* __restrict__ bmu, const float* __restrict__ bls) {
    int i = blockIdx.x * 256 + threadIdx.x;   // grid covers 65536
    if (i < NN) { g_deg[i] = 1; g_cur[i] = 0; }
    if (i < 256) g_bcat[i] = (i < 128) ? bmu[i] : bls[i - 128];
    int k = i >> 8, c = i & 255;
    g_Wcat[i] = (c < 128) ? Wmu[k * 128 + c] : Wls[k * 128 + (c - 128)];
}
__global__ void count_kernel(const int* __restrict__ dst) {
    int e = blockIdx.x * blockDim.x + threadIdx.x;
    if (e < NE) atomicAdd(&g_deg[dst[e]], 1);
}
__global__ void blocksum_kernel() {
    int i = blockIdx.x * 256 + threadIdx.x;
    int d = (i < NN) ? g_deg[i] : 1;
    if (i < NN) {
        float r = rsqrtf((float)d);
        g_dinv[i]  = r;
        g_dinvh[i] = __float2half_rn(r);
    }
    int v = (i < NN) ? d - 1 : 0;
#pragma unroll
    for (int o = 16; o; o >>= 1) v += __shfl_down_sync(0xffffffffu, v, o);
    __shared__ int ws[8];
    if ((threadIdx.x & 31) == 0) ws[threadIdx.x >> 5] = v;
    __syncthreads();
    if (threadIdx.x < 8) {
        int s = ws[threadIdx.x];
#pragma unroll
        for (int o = 4; o; o >>= 1) s += __shfl_down_sync(0xffu, s, o);
        if (threadIdx.x == 0) g_bsum[blockIdx.x] = s;
    }
}
__global__ void bscan_kernel() {
    __shared__ int sh[256];
    int t = threadIdx.x;
    int v = (t < NB) ? g_bsum[t] : 0;
    sh[t] = v; __syncthreads();
    for (int o = 1; o < 256; o <<= 1) {
        int u = (t >= o) ? sh[t - o] : 0;
        __syncthreads(); sh[t] += u; __syncthreads();
    }
    if (t < NB) g_boff[t] = sh[t] - v;
}
__global__ void offsets_kernel() {
    __shared__ int sh[256];
    int b = blockIdx.x, t = threadIdx.x;
    int i = b * 256 + t;
    int v = (i < NN) ? g_deg[i] - 1 : 0;
    sh[t] = v; __syncthreads();
    for (int o = 1; o < 256; o <<= 1) {
        int u = (t >= o) ? sh[t - o] : 0;
        __syncthreads(); sh[t] += u; __syncthreads();
    }
    int excl = sh[t] - v + g_boff[b];
    if (i < NN)      g_off[i]  = excl;
    if (i == NN - 1) g_off[NN] = excl + v;
}
__global__ void fill_kernel(const int* __restrict__ src, const int* __restrict__ dst) {
    int e = blockIdx.x * blockDim.x + threadIdx.x;
    if (e < NE) {
        int d = dst[e];
        int pos = g_off[d] + atomicAdd(&g_cur[d], 1);
        g_csr[pos] = src[e];
    }
}

// ---------------- agg1: T -> H' (weights dinvh[s]; out pre-scaled by dinv) --
__global__ void agg1_kernel(const __half2* __restrict__ F, __half2* __restrict__ O,
                            const float* __restrict__ bias) {
    int gw = (blockIdx.x * blockDim.x + threadIdx.x) >> 5;
    if (gw >= NN) return;
    int lane = threadIdx.x & 31;

    float di = g_dinv[gw];
    float a[8];
    {
        uint4 v = *((const uint4*)(F + (size_t)gw * 128) + lane);
        const __half2* h = (const __half2*)&v;
#pragma unroll
        for (int j = 0; j < 4; j++) {
            float2 f = __half22float2(h[j]);
            a[2 * j]     = di * f.x;
            a[2 * j + 1] = di * f.y;
        }
    }

    int e = g_off[gw];
    const int eend = g_off[gw + 1];
    const __half2 hz = __floats2half2_rn(0.f, 0.f);

    while (e + 8 <= eend) {
        int s[8];
#pragma unroll
        for (int i = 0; i < 8; i++) s[i] = g_csr[e + i];
        __half2 w2[8]; uint4 v[8];
#pragma unroll
        for (int i = 0; i < 8; i++) {
            w2[i] = __half2half2(g_dinvh[s[i]]);
            v[i]  = *((const uint4*)(F + (size_t)s[i] * 128) + lane);
        }
        __half2 pa0 = hz, pa1 = hz, pa2 = hz, pa3 = hz;
        __half2 pb0 = hz, pb1 = hz, pb2 = hz, pb3 = hz;
#pragma unroll
        for (int i = 0; i < 4; i++) {
            const __half2* h = (const __half2*)&v[i];
            pa0 = __hfma2(h[0], w2[i], pa0);
            pa1 = __hfma2(h[1], w2[i], pa1);
            pa2 = __hfma2(h[2], w2[i], pa2);
            pa3 = __hfma2(h[3], w2[i], pa3);
        }
#pragma unroll
        for (int i = 4; i < 8; i++) {
            const __half2* h = (const __half2*)&v[i];
            pb0 = __hfma2(h[0], w2[i], pb0);
            pb1 = __hfma2(h[1], w2[i], pb1);
            pb2 = __hfma2(h[2], w2[i], pb2);
            pb3 = __hfma2(h[3], w2[i], pb3);
        }
        float2 fa0 = __half22float2(pa0), fa1 = __half22float2(pa1);
        float2 fa2 = __half22float2(pa2), fa3 = __half22float2(pa3);
        float2 fb0 = __half22float2(pb0), fb1 = __half22float2(pb1);
        float2 fb2 = __half22float2(pb2), fb3 = __half22float2(pb3);
        a[0] += fa0.x + fb0.x; a[1] += fa0.y + fb0.y;
        a[2] += fa1.x + fb1.x; a[3] += fa1.y + fb1.y;
        a[4] += fa2.x + fb2.x; a[5] += fa2.y + fb2.y;
        a[6] += fa3.x + fb3.x; a[7] += fa3.y + fb3.y;
        e += 8;
    }
    if (e + 4 <= eend) {
        __half2 p0 = hz, p1 = hz, p2 = hz, p3 = hz;
#pragma unroll
        for (int i = 0; i < 4; i++) {
            int s = g_csr[e + i];
            __half2 w2 = __half2half2(g_dinvh[s]);
            uint4 v = *((const uint4*)(F + (size_t)s * 128) + lane);
            const __half2* h = (const __half2*)&v;
            p0 = __hfma2(h[0], w2, p0);
            p1 = __hfma2(h[1], w2, p1);
            p2 = __hfma2(h[2], w2, p2);
            p3 = __hfma2(h[3], w2, p3);
        }
        float2 f0 = __half22float2(p0), f1 = __half22float2(p1);
        float2 f2 = __half22float2(p2), f3 = __half22float2(p3);
        a[0] += f0.x; a[1] += f0.y; a[2] += f1.x; a[3] += f1.y;
        a[4] += f2.x; a[5] += f2.y; a[6] += f3.x; a[7] += f3.y;
        e += 4;
    }
    for (; e < eend; e++) {
        int s = g_csr[e];
        float w = __half2float(g_dinvh[s]);
        uint4 v = *((const uint4*)(F + (size_t)s * 128) + lane);
        const __half2* h = (const __half2*)&v;
#pragma unroll
        for (int j = 0; j < 4; j++) {
            float2 f = __half22float2(h[j]);
            a[2 * j]     += w * f.x;
            a[2 * j + 1] += w * f.y;
        }
    }

    // epilogue: H' = dinv_i * relu(di * agg + bias)   (pre-scaled for agg2)
    const float4* bp = (const float4*)bias + lane * 2;
    float4 b0 = bp[0], b1 = bp[1];
    float bb[8] = {b0.x, b0.y, b0.z, b0.w, b1.x, b1.y, b1.z, b1.w};
    uint4 o;
    __half2* oh = (__half2*)&o;
#pragma unroll
    for (int j = 0; j < 4; j++) {
        float x0 = di * fmaxf(a[2 * j]     * di + bb[2 * j],     0.f);
        float x1 = di * fmaxf(a[2 * j + 1] * di + bb[2 * j + 1], 0.f);
        oh[j] = __floats2half2_rn(x0, x1);
    }
    *((uint4*)O + (size_t)gw * 32 + lane) = o;
}

// ---------------- agg2: G = dinv_i * (H'_i + sum_s H'_s)  (NO weight loads) -
__global__ void agg2_kernel(const __half2* __restrict__ F, __half2* __restrict__ O) {
    int gw = (blockIdx.x * blockDim.x + threadIdx.x) >> 5;
    if (gw >= NN) return;
    int lane = threadIdx.x & 31;

    float di = g_dinv[gw];
    float a[8];
    {
        // self row H'_i (already carries dinv_i factor)
        uint4 v = *((const uint4*)(F + (size_t)gw * 128) + lane);
        const __half2* h = (const __half2*)&v;
#pragma unroll
        for (int j = 0; j < 4; j++) {
            float2 f = __half22float2(h[j]);
            a[2 * j]     = f.x;
            a[2 * j + 1] = f.y;
        }
    }

    int e = g_off[gw];
    const int eend = g_off[gw + 1];
    const __half2 hz = __floats2half2_rn(0.f, 0.f);

    while (e + 8 <= eend) {
        int s[8];
#pragma unroll
        for (int i = 0; i < 8; i++) s[i] = g_csr[e + i];
        uint4 v[8];
#pragma unroll
        for (int i = 0; i < 8; i++)
            v[i] = *((const uint4*)(F + (size_t)s[i] * 128) + lane);
        __half2 pa0 = hz, pa1 = hz, pa2 = hz, pa3 = hz;
        __half2 pb0 = hz, pb1 = hz, pb2 = hz, pb3 = hz;
#pragma unroll
        for (int i = 0; i < 4; i++) {
            const __half2* h = (const __half2*)&v[i];
            pa0 = __hadd2(pa0, h[0]);
            pa1 = __hadd2(pa1, h[1]);
            pa2 = __hadd2(pa2, h[2]);
            pa3 = __hadd2(pa3, h[3]);
        }
#pragma unroll
        for (int i = 4; i < 8; i++) {
            const __half2* h = (const __half2*)&v[i];
            pb0 = __hadd2(pb0, h[0]);
            pb1 = __hadd2(pb1, h[1]);
            pb2 = __hadd2(pb2, h[2]);
            pb3 = __hadd2(pb3, h[3]);
        }
        float2 fa0 = __half22float2(pa0), fa1 = __half22float2(pa1);
        float2 fa2 = __half22float2(pa2), fa3 = __half22float2(pa3);
        float2 fb0 = __half22float2(pb0), fb1 = __half22float2(pb1);
        float2 fb2 = __half22float2(pb2), fb3 = __half22float2(pb3);
        a[0] += fa0.x + fb0.x; a[1] += fa0.y + fb0.y;
        a[2] += fa1.x + fb1.x; a[3] += fa1.y + fb1.y;
        a[4] += fa2.x + fb2.x; a[5] += fa2.y + fb2.y;
        a[6] += fa3.x + fb3.x; a[7] += fa3.y + fb3.y;
        e += 8;
    }
    if (e + 4 <= eend) {
        __half2 p0 = hz, p1 = hz, p2 = hz, p3 = hz;
#pragma unroll
        for (int i = 0; i < 4; i++) {
            int s = g_csr[e + i];
            uint4 v = *((const uint4*)(F + (size_t)s * 128) + lane);
            const __half2* h = (const __half2*)&v;
            p0 = __hadd2(p0, h[0]);
            p1 = __hadd2(p1, h[1]);
            p2 = __hadd2(p2, h[2]);
            p3 = __hadd2(p3, h[3]);
        }
        float2 f0 = __half22float2(p0), f1 = __half22float2(p1);
        float2 f2 = __half22float2(p2), f3 = __half22float2(p3);
        a[0] += f0.x; a[1] += f0.y; a[2] += f1.x; a[3] += f1.y;
        a[4] += f2.x; a[5] += f2.y; a[6] += f3.x; a[7] += f3.y;
        e += 4;
    }
    for (; e < eend; e++) {
        int s = g_csr[e];
        uint4 v = *((const uint4*)(F + (size_t)s * 128) + lane);
        const __half2* h = (const __half2*)&v;
#pragma unroll
        for (int j = 0; j < 4; j++) {
            float2 f = __half22float2(h[j]);
            a[2 * j]     += f.x;
            a[2 * j + 1] += f.y;
        }
    }

    uint4 o;
    __half2* oh = (__half2*)&o;
#pragma unroll
    for (int j = 0; j < 4; j++)
        oh[j] = __floats2half2_rn(a[2 * j] * di, a[2 * j + 1] * di);
    *((uint4*)O + (size_t)gw * 32 + lane) = o;
}

// ---------------- FP16 tensor-core GEMM (m16n8k16, fp32 accum) -------------
__device__ __forceinline__ void mma_f16(float* d, const uint32_t* a, const uint32_t* b) {
    asm volatile(
        "mma.sync.aligned.m16n8k16.row.col.f32.f16.f16.f32 "
        "{%0,%1,%2,%3}, {%4,%5,%6,%7}, {%8,%9}, {%0,%1,%2,%3};"
        : "+f"(d[0]), "+f"(d[1]), "+f"(d[2]), "+f"(d[3])
        : "r"(a[0]), "r"(a[1]), "r"(a[2]), "r"(a[3]), "r"(b[0]), "r"(b[1]));
}

#define GBM 128
#define ASTRIDE 20
#define BSTRIDE 136

template <int MODE>
__global__ __launch_bounds__(256) void h16gemm_kernel(
    const void* __restrict__ Ain, const float* __restrict__ B,
    const float* __restrict__ bias, void* __restrict__ Cout, int M) {
    __shared__ uint32_t As[GBM * ASTRIDE];
    __shared__ uint32_t Bs[16 * BSTRIDE];

    const int t = threadIdx.x;
    const int lane = t & 31;
    const int warp = t >> 5;
    const int warpM = warp >> 2;
    const int warpN = warp & 3;
    const int l4 = lane >> 2, k4 = lane & 3;
    const int rowBase = blockIdx.x * GBM;
    const int colBase = blockIdx.y * 128;
    const int mBase = warpM * 64;
    const int nBase = warpN * 32;

    const int aRow  = (MODE == 0) ? (t >> 3) : (t >> 2);
    const int aK2   = (MODE == 0) ? ((t & 7) << 1) : ((t & 3) << 2);
    const int bK2 = t >> 5;
    const int bNc = (t & 31) << 2;

    const uint32_t asBase = (uint32_t)__cvta_generic_to_shared(As);
    const int lmRow = lane & 15;
    const int lmK   = (lane >> 4) << 2;

    float4 raf[4]; uint4 rah[2]; float4 rb0[2], rb1[2];
#pragma unroll
    for (int l = 0; l < 2; l++) {
        int k2 = bK2 + l * 8;
        rb0[l] = *(const float4*)(B + (size_t)(2 * k2)     * 256 + colBase + bNc);
        rb1[l] = *(const float4*)(B + (size_t)(2 * k2 + 1) * 256 + colBase + bNc);
    }
    if (MODE == 0) {
        const float* A = (const float*)Ain;
#pragma unroll
        for (int l = 0; l < 4; l++) {
            int gr = rowBase + aRow + l * 32;
            raf[l] = (gr < M) ? *(const float4*)(A + (size_t)gr * 256 + aK2 * 2)
                              : make_float4(0.f, 0.f, 0.f, 0.f);
        }
    } else {
        const __half2* A = (const __half2*)Ain;
#pragma unroll
        for (int l = 0; l < 2; l++) {
            int gr = rowBase + aRow + l * 64;
            rah[l] = (gr < M) ? *((const uint4*)(A + (size_t)gr * 128) + (aK2 >> 2))
                              : make_uint4(0u, 0u, 0u, 0u);
        }
    }

    float acc[4][4][4];
#pragma unroll
    for (int i = 0; i < 4; i++)
#pragma unroll
        for (int j = 0; j < 4; j++)
#pragma unroll
            for (int r = 0; r < 4; r++) acc[i][j][r] = 0.f;

    for (int it = 0; it < 8; it++) {
        if (MODE == 0) {
#pragma unroll
            for (int l = 0; l < 4; l++) {
                uint32_t* p = &As[(aRow + l * 32) * ASTRIDE + aK2];
                p[0] = h2u(__floats2half2_rn(raf[l].x, raf[l].y));
                p[1] = h2u(__floats2half2_rn(raf[l].z, raf[l].w));
            }
        } else {
#pragma unroll
            for (int l = 0; l < 2; l++)
                *(uint4*)&As[(aRow + l * 64) * ASTRIDE + aK2] = rah[l];
        }
#pragma unroll
        for (int l = 0; l < 2; l++) {
            uint4 u;
            u.x = h2u(__floats2half2_rn(rb0[l].x, rb1[l].x));
            u.y = h2u(__floats2half2_rn(rb0[l].y, rb1[l].y));
            u.z = h2u(__floats2half2_rn(rb0[l].z, rb1[l].z));
            u.w = h2u(__floats2half2_rn(rb0[l].w, rb1[l].w));
            *(uint4*)&Bs[(bK2 + l * 8) * BSTRIDE + bNc] = u;
        }
        __syncthreads();

        if (it < 7) {
            int k0 = (it + 1) * 32;
#pragma unroll
            for (int l = 0; l < 2; l++) {
                int k2 = (k0 >> 1) + bK2 + l * 8;
                rb0[l] = *(const float4*)(B + (size_t)(2 * k2)     * 256 + colBase + bNc);
                rb1[l] = *(const float4*)(B + (size_t)(2 * k2 + 1) * 256 + colBase + bNc);
            }
            if (MODE == 0) {
                const float* A = (const float*)Ain;
#pragma unroll
                for (int l = 0; l < 4; l++) {
                    int gr = rowBase + aRow + l * 32;
                    raf[l] = (gr < M) ? *(const float4*)(A + (size_t)gr * 256 + k0 + aK2 * 2)
                                      : make_float4(0.f, 0.f, 0.f, 0.f);
                }
            } else {
                const __half2* A = (const __half2*)Ain;
#pragma unroll
                for (int l = 0; l < 2; l++) {
                    int gr = rowBase + aRow + l * 64;
                    rah[l] = (gr < M) ? *((const uint4*)(A + (size_t)gr * 128) + ((k0 >> 1) + aK2) / 4)
                                      : make_uint4(0u, 0u, 0u, 0u);
                }
            }
        }

#pragma unroll
        for (int ks = 0; ks < 16; ks += 8) {
            uint32_t af[4][4], bf[4][2];
#pragma unroll
            for (int mi = 0; mi < 4; mi++) {
                uint32_t sa = asBase +
                    4u * ((uint32_t)(mBase + mi * 16 + lmRow) * ASTRIDE + ks + lmK);
                ldsm_x4(af[mi], sa);
            }
#pragma unroll
            for (int ni = 0; ni < 4; ni++) {
                int n = nBase + ni * 8 + l4;
                bf[ni][0] = Bs[(ks + k4) * BSTRIDE + n];
                bf[ni][1] = Bs[(ks + k4 + 4) * BSTRIDE + n];
            }
#pragma unroll
            for (int mi = 0; mi < 4; mi++)
#pragma unroll
                for (int ni = 0; ni < 4; ni++)
                    mma_f16(acc[mi][ni], af[mi], bf[ni]);
        }
        __syncthreads();
    }

#pragma unroll
    for (int mi = 0; mi < 4; mi++) {
        int r0 = rowBase + mBase + mi * 16 + l4;
        int r1 = r0 + 8;
#pragma unroll
        for (int ni = 0; ni < 4; ni++) {
            int cl = nBase + ni * 8 + k4 * 2;
            if (MODE == 0) {
                __half2* T = (__half2*)Cout;
                int c = colBase + cl;
                if (r0 < M) T[(size_t)r0 * 128 + (c >> 1)] =
                    __floats2half2_rn(acc[mi][ni][0], acc[mi][ni][1]);
                if (r1 < M) T[(size_t)r1 * 128 + (c >> 1)] =
                    __floats2half2_rn(acc[mi][ni][2], acc[mi][ni][3]);
            } else {
                float* Co = (float*)Cout + (blockIdx.y ? (size_t)NN * 128 : 0);
                float bv0 = bias[colBase + cl];
                float bv1 = bias[colBase + cl + 1];
                if (r0 < M) {
                    float2 o; o.x = acc[mi][ni][0] + bv0; o.y = acc[mi][ni][1] + bv1;
                    *(float2*)(Co + (size_t)r0 * 128 + cl) = o;
                }
                if (r1 < M) {
                    float2 o; o.x = acc[mi][ni][2] + bv0; o.y = acc[mi][ni][3] + bv1;
                    *(float2*)(Co + (size_t)r1 * 128 + cl) = o;
                }
            }
        }
    }
}

// ---------------- launch: fork prep || GEMM1, join before agg ---------------
extern "C" void kernel_launch(void* const* d_in, const int* in_sizes, int n_in,
                              void* d_out, int out_size) {
    const float* x    = (const float*)d_in[0];
    const int*   ei   = (const int*)d_in[1];
    const float* W1   = (const float*)d_in[2];
    const float* b1   = (const float*)d_in[3];
    const float* Wmu  = (const float*)d_in[4];
    const float* bmu  = (const float*)d_in[5];
    const float* Wls  = (const float*)d_in[6];
    const float* bls  = (const float*)d_in[7];
    float* out = (float*)d_out;

    const int* src = ei;
    const int* dst = ei + NE;

    __half2 *pT, *pH, *pG; float *pWcat, *pbcat;
    cudaGetSymbolAddress((void**)&pT, g_T);
    cudaGetSymbolAddress((void**)&pH, g_H);
    cudaGetSymbolAddress((void**)&pG, g_G);
    cudaGetSymbolAddress((void**)&pWcat, g_Wcat);
    cudaGetSymbolAddress((void**)&pbcat, g_bcat);

    cudaStream_t s1;
    cudaEvent_t evFork, evJoin;
    cudaStreamCreateWithFlags(&s1, cudaStreamNonBlocking);
    cudaEventCreateWithFlags(&evFork, cudaEventDisableTiming);
    cudaEventCreateWithFlags(&evJoin, cudaEventDisableTiming);

    cudaEventRecord(evFork, 0);
    cudaStreamWaitEvent(s1, evFork, 0);

    // side stream: graph prep (6 launches)
    initwcat_kernel<<<256, 256, 0, s1>>>(Wmu, Wls, bmu, bls);
    count_kernel<<<(NE + 255) / 256, 256, 0, s1>>>(dst);
    blocksum_kernel<<<NB, 256, 0, s1>>>();
    bscan_kernel<<<1, 256, 0, s1>>>();
    offsets_kernel<<<NB, 256, 0, s1>>>();
    fill_kernel<<<(NE + 255) / 256, 256, 0, s1>>>(src, dst);
    cudaEventRecord(evJoin, s1);

    // main stream: T = x @ W1
    dim3 ggrid((NN + GBM - 1) / GBM, 2);
    h16gemm_kernel<0><<<ggrid, 256>>>(x, W1, nullptr, pT, NN);

    cudaStreamWaitEvent(0, evJoin, 0);
    agg1_kernel<<<(NN * 32 + 255) / 256, 256>>>(pT, pH, b1);
    agg2_kernel<<<(NN * 32 + 255) / 256, 256>>>(pH, pG);
    h16gemm_kernel<1><<<ggrid, 256>>>(pG, pWcat, pbcat, out, NN);
}